// round 11
// baseline (speedup 1.0000x reference)
#include <cuda_runtime.h>

// Problem constants
#define BB 256      // batch
#define TT 2000     // seq len
#define HH 64       // hidden
#define G4 256      // 4*H
#define VV 2000     // vocab

// Scratch (allocation-free rule: __device__ globals)
// transposed projection table: projT[v][u*4 + g], g in {i,f,g,o}, prescaled
__device__ float g_projT[(size_t)VV * G4];
__device__ float g_hf[BB * HH];

typedef unsigned long long u64;

__device__ __forceinline__ u64 fma2(u64 a, u64 b, u64 c) {
    u64 d;
    asm("fma.rn.f32x2 %0, %1, %2, %3;" : "=l"(d) : "l"(a), "l"(b), "l"(c));
    return d;
}
__device__ __forceinline__ u64 add2(u64 a, u64 b) {
    u64 d;
    asm("add.rn.f32x2 %0, %1, %2;" : "=l"(d) : "l"(a), "l"(b));
    return d;
}
__device__ __forceinline__ u64 pack2(float lo, float hi) {
    u64 d;
    asm("mov.b64 %0, {%1, %2};" : "=l"(d) : "f"(lo), "f"(hi));
    return d;
}
__device__ __forceinline__ float hsum2(u64 a) {
    float lo, hi;
    asm("mov.b64 {%0, %1}, %2;" : "=f"(lo), "=f"(hi) : "l"(a));
    return lo + hi;
}
__device__ __forceinline__ float ex2_(float x) {
    float r; asm("ex2.approx.f32 %0, %1;" : "=f"(r) : "f"(x)); return r;
}
__device__ __forceinline__ float rcp_(float x) {
    float r; asm("rcp.approx.f32 %0, %1;" : "=f"(r) : "f"(x)); return r;
}
__device__ __forceinline__ float tanha_(float x) {
    float r; asm("tanh.approx.f32 %0, %1;" : "=f"(r) : "f"(x)); return r;
}
__device__ __forceinline__ float sigmoid_(float x) {
    return rcp_(1.0f + ex2_(-1.4426950408889634f * x));
}
__device__ __forceinline__ float tanh_(float x) {
    return fmaf(2.0f, rcp_(1.0f + ex2_(-2.8853900817779268f * x)), -1.0f);
}
__device__ __forceinline__ void barrow(int row) {
    asm volatile("bar.sync %0, 64;" :: "r"(row + 1) : "memory");
}

// no-op kernels: keep ncu's capture slot (-s 5 -c 1) on k_scan (our 4th launch)
__global__ void k_nop() {}

// ---------------------------------------------------------------------------
// K0: projT[v][u*4+g] = sg_g * (emb[v] . w_ih_f[g*64+u] + b_ih_f + b_hh_f)
// sg = 0.5 for sigmoid gates (i,f,o), 1.0 for candidate (g). Transposed
// layout -> scan reads one float4 per thread per step.
// ---------------------------------------------------------------------------
__global__ void __launch_bounds__(256) k_proj(
    const float* __restrict__ emb, const float* __restrict__ w,
    const float* __restrict__ b1, const float* __restrict__ b2)
{
    __shared__ __align__(16) float sh_e[8 * 64];
    const int j = threadIdx.x;            // gate-row index g*64+u
    const int u = j & 63, g = j >> 6;

    u64 w2[32];
#pragma unroll
    for (int k2 = 0; k2 < 32; ++k2) {
        float2 wv = *(const float2*)&w[j * 64 + 2 * k2];
        w2[k2] = pack2(wv.x, wv.y);
    }
    const float bias = b1[j] + b2[j];
    const float sg = (g == 2) ? 1.0f : 0.5f;

    const int v0 = blockIdx.x * 8;
#pragma unroll
    for (int i = j; i < 512; i += 256) {
        int r = i >> 6, k = i & 63;
        int v = v0 + r;
        sh_e[i] = (v == 0 || v >= VV) ? 0.0f : emb[v * HH + k];
    }
    __syncthreads();
    const ulonglong2* ep = (const ulonglong2*)sh_e;
#pragma unroll
    for (int r = 0; r < 8; ++r) {
        int v = v0 + r;
        if (v >= VV) break;
        u64 acc = 0ull;
#pragma unroll
        for (int k4 = 0; k4 < 16; ++k4) {
            ulonglong2 ev = ep[r * 16 + k4];
            acc = fma2(w2[2 * k4], ev.x, acc);
            acc = fma2(w2[2 * k4 + 1], ev.y, acc);
        }
        g_projT[(size_t)v * G4 + u * 4 + g] = sg * (hsum2(acc) + bias);
    }
}

// ---------------------------------------------------------------------------
// K2: forward LSTM scan — gate-major, shfl-free.
// 64 CTAs x 256 threads; CTA owns 4 batch rows. Row r = threads [64r,64r+64)
// = warps 2r,2r+1 (2-warp named barrier per row -> minimal convoy). Each
// SMSP holds 2 warps from DIFFERENT rows (independent chains). Thread owns
// ONE unit u with ALL 4 gates: weights = 4 gate rows in regs, cell update
// fully thread-local (no shfl, unconditional STS.32). Transposed proj table
// gives one LDG.128 input fetch per step. Ping-pong h, branch-free loop
// (padded x, peeled last step), tanh.approx activations, 0.5 pre-scale in
// weights/proj for sigmoid gates.
// ---------------------------------------------------------------------------
__global__ void __launch_bounds__(256, 1) k_scan(
    const int* __restrict__ x, const float* __restrict__ whh)
{
    __shared__ __align__(16) float h_sh[2][4][64];  // [buf][row][unit]
    __shared__ int xs[4][TT + 2];                   // per-row indices, padded
    const int tid = threadIdx.x;
    const int row = tid >> 6;              // 0..3: row within CTA
    const int u = tid & 63;                // unit owned by this thread
    const int b = blockIdx.x * 4 + row;

    // stage x indices for 4 rows (coalesced along t), pad 2 trailing entries
    {
        const int* xr = x + (size_t)(blockIdx.x * 4) * TT;
        for (int i = tid; i < 4 * TT; i += 256)
            xs[i / TT][i % TT] = xr[i];
        if (tid < 8)
            xs[tid >> 1][TT + (tid & 1)] = xr[(tid >> 1) * TT + TT - 1];
    }

    // weights: 4 gate rows for unit u (i,f,o prescaled by 0.5; g unscaled)
    u64 wi[16], wf[16], wg[16], wo[16];
#pragma unroll
    for (int k2 = 0; k2 < 16; ++k2) {
        float2 vi0 = *(const float2*)&whh[(0 * 64 + u) * 64 + 4 * k2];
        float2 vi1 = *(const float2*)&whh[(0 * 64 + u) * 64 + 4 * k2 + 2];
        (void)vi1;
    }
    // load as 32 f32x2 per gate packed into 16 u64 of 4 floats? No — keep
    // 32 u64 per gate is too many; use 64-float rows as 32 u64 halves:
    // actually: 64 floats = 32 f32x2 pairs. We need 32 u64 per gate -> 128
    // total. Pack two k-pairs per unrolled iteration instead:
    u64 wia[32], wfa[32], wga[32], woa[32];
#pragma unroll
    for (int k2 = 0; k2 < 32; ++k2) {
        float2 a = *(const float2*)&whh[(0 * 64 + u) * 64 + 2 * k2];
        float2 bq = *(const float2*)&whh[(1 * 64 + u) * 64 + 2 * k2];
        float2 cq = *(const float2*)&whh[(2 * 64 + u) * 64 + 2 * k2];
        float2 dq = *(const float2*)&whh[(3 * 64 + u) * 64 + 2 * k2];
        wia[k2] = pack2(0.5f * a.x, 0.5f * a.y);
        wfa[k2] = pack2(0.5f * bq.x, 0.5f * bq.y);
        wga[k2] = pack2(cq.x, cq.y);
        woa[k2] = pack2(0.5f * dq.x, 0.5f * dq.y);
    }

    // zero step-0 read buffer
    h_sh[0][row][u] = 0.0f;
    float c = 0.0f;

    const float* __restrict__ projT = g_projT;
    const int* xsh = xs[row];

    __syncthreads();  // x stage + h init visible (all rows once)

    // distance-2 prefetch: one float4 (i,f,g,o prescaled) per step
    float4 xc = *(const float4*)&projT[(size_t)xsh[0] * G4 + u * 4];
    float4 xn = *(const float4*)&projT[(size_t)xsh[1] * G4 + u * 4];

#pragma unroll 2
    for (int t = 0; t < TT - 1; ++t) {
        float4 xf = *(const float4*)&projT[(size_t)xsh[t + 2] * G4 + u * 4];

        // 4 gate dots over h[0..63] (2 chains of 16 per gate)
        const ulonglong2* hp = (const ulonglong2*)h_sh[t & 1][row];
        u64 i0 = 0ull, i1 = 0ull, f0 = 0ull, f1 = 0ull;
        u64 g0 = 0ull, g1 = 0ull, o0 = 0ull, o1 = 0ull;
#pragma unroll
        for (int k4 = 0; k4 < 8; ++k4) {
            ulonglong2 h0 = hp[k4];        // h[4k4 .. 4k4+3]
            ulonglong2 h1 = hp[8 + k4];    // h[32+4k4 ..]
            i0 = fma2(wia[2 * k4],      h0.x, i0);
            i1 = fma2(wia[2 * k4 + 1],  h0.y, i1);
            f0 = fma2(wfa[2 * k4],      h0.x, f0);
            f1 = fma2(wfa[2 * k4 + 1],  h0.y, f1);
            g0 = fma2(wga[2 * k4],      h0.x, g0);
            g1 = fma2(wga[2 * k4 + 1],  h0.y, g1);
            o0 = fma2(woa[2 * k4],      h0.x, o0);
            o1 = fma2(woa[2 * k4 + 1],  h0.y, o1);
            i0 = fma2(wia[16 + 2 * k4], h1.x, i0);
            i1 = fma2(wia[17 + 2 * k4], h1.y, i1);
            f0 = fma2(wfa[16 + 2 * k4], h1.x, f0);
            f1 = fma2(wfa[17 + 2 * k4], h1.y, f1);
            g0 = fma2(wga[16 + 2 * k4], h1.x, g0);
            g1 = fma2(wga[17 + 2 * k4], h1.y, g1);
            o0 = fma2(woa[16 + 2 * k4], h1.x, o0);
            o1 = fma2(woa[17 + 2 * k4], h1.y, o1);
        }
        float pi = hsum2(add2(i0, i1)) + xc.x;
        float pf = hsum2(add2(f0, f1)) + xc.y;
        float pg = hsum2(add2(g0, g1)) + xc.z;
        float po = hsum2(add2(o0, o1)) + xc.w;

        // activations (sigmoid = 0.5*tanh(0.5x)+0.5, 0.5 already folded)
        float iv = fmaf(0.5f, tanha_(pi), 0.5f);
        float fv = fmaf(0.5f, tanha_(pf), 0.5f);
        float gv = tanha_(pg);
        float ov = fmaf(0.5f, tanha_(po), 0.5f);

        // thread-local cell update — no exchange needed
        c = fv * c + iv * gv;
        h_sh[(t + 1) & 1][row][u] = ov * tanha_(c);
        barrow(row);                        // 2-warp named barrier

        xc = xn; xn = xf;
    }

    // peeled final step t = TT-1: write h straight to global
    {
        const ulonglong2* hp = (const ulonglong2*)h_sh[(TT - 1) & 1][row];
        u64 i0 = 0ull, i1 = 0ull, f0 = 0ull, f1 = 0ull;
        u64 g0 = 0ull, g1 = 0ull, o0 = 0ull, o1 = 0ull;
#pragma unroll
        for (int k4 = 0; k4 < 8; ++k4) {
            ulonglong2 h0 = hp[k4];
            ulonglong2 h1 = hp[8 + k4];
            i0 = fma2(wia[2 * k4],      h0.x, i0);
            i1 = fma2(wia[2 * k4 + 1],  h0.y, i1);
            f0 = fma2(wfa[2 * k4],      h0.x, f0);
            f1 = fma2(wfa[2 * k4 + 1],  h0.y, f1);
            g0 = fma2(wga[2 * k4],      h0.x, g0);
            g1 = fma2(wga[2 * k4 + 1],  h0.y, g1);
            o0 = fma2(woa[2 * k4],      h0.x, o0);
            o1 = fma2(woa[2 * k4 + 1],  h0.y, o1);
            i0 = fma2(wia[16 + 2 * k4], h1.x, i0);
            i1 = fma2(wia[17 + 2 * k4], h1.y, i1);
            f0 = fma2(wfa[16 + 2 * k4], h1.x, f0);
            f1 = fma2(wfa[17 + 2 * k4], h1.y, f1);
            g0 = fma2(wga[16 + 2 * k4], h1.x, g0);
            g1 = fma2(wga[17 + 2 * k4], h1.y, g1);
            o0 = fma2(woa[16 + 2 * k4], h1.x, o0);
            o1 = fma2(woa[17 + 2 * k4], h1.y, o1);
        }
        float pi = hsum2(add2(i0, i1)) + xc.x;
        float pf = hsum2(add2(f0, f1)) + xc.y;
        float pg = hsum2(add2(g0, g1)) + xc.z;
        float po = hsum2(add2(o0, o1)) + xc.w;
        float iv = fmaf(0.5f, tanha_(pi), 0.5f);
        float fv = fmaf(0.5f, tanha_(pf), 0.5f);
        float gv = tanha_(pg);
        float ov = fmaf(0.5f, tanha_(po), 0.5f);
        c = fv * c + iv * gv;
        g_hf[b * HH + u] = ov * tanha_(c);
    }
}

// ---------------------------------------------------------------------------
// K3: fused tail. One block per batch row:
//   1) backward LSTM single step (hs_b[0]) from zero state at t=T-1
//   2) fc: out[b][c] = concat(hf[b], hb[b]) . w_fc[c] + b_fc[c]
// ---------------------------------------------------------------------------
__global__ void __launch_bounds__(256) k_tail(
    const int* __restrict__ x, const float* __restrict__ emb,
    const float* __restrict__ w, const float* __restrict__ b1,
    const float* __restrict__ b2, const float* __restrict__ wfc,
    const float* __restrict__ bfc, float* __restrict__ out)
{
    __shared__ __align__(16) float e_sh[64];
    __shared__ float g_sh[256];
    __shared__ float hb_sh[64];
    const int j = threadIdx.x;
    const int b = blockIdx.x;

    if (j < 64) {
        int idx = x[b * TT + (TT - 1)];
        e_sh[j] = (idx == 0) ? 0.0f : emb[idx * HH + j];
    }
    __syncthreads();

    float acc = b1[j] + b2[j];
    const ulonglong2* ep = (const ulonglong2*)e_sh;
    u64 a2 = 0ull;
#pragma unroll
    for (int k4 = 0; k4 < 16; ++k4) {
        float2 wv0 = *(const float2*)&w[j * 64 + 4 * k4];
        float2 wv1 = *(const float2*)&w[j * 64 + 4 * k4 + 2];
        ulonglong2 ev = ep[k4];
        a2 = fma2(pack2(wv0.x, wv0.y), ev.x, a2);
        a2 = fma2(pack2(wv1.x, wv1.y), ev.y, a2);
    }
    acc += hsum2(a2);

    const int gate = j >> 6;
    g_sh[j] = (gate == 2) ? tanh_(acc) : sigmoid_(acc);
    __syncthreads();

    if (j < 64) {
        float iv = g_sh[j];
        float gv = g_sh[128 + j];
        float ov = g_sh[192 + j];
        float cc = iv * gv;               // f*c0 = 0
        hb_sh[j] = ov * tanh_(cc);
    }
    __syncthreads();

    if (j < 12) {
        float s = bfc[j];
        const float* hf = g_hf + b * HH;
#pragma unroll
        for (int k = 0; k < 64; ++k)
            s += hf[k] * wfc[j * 128 + k];
#pragma unroll
        for (int k = 0; k < 64; ++k)
            s += hb_sh[k] * wfc[j * 128 + 64 + k];
        out[b * 12 + j] = s;
    }
}

// ---------------------------------------------------------------------------
extern "C" void kernel_launch(void* const* d_in, const int* in_sizes, int n_in,
                              void* d_out, int out_size)
{
    const int*   x      = (const int*)d_in[0];
    const float* emb    = (const float*)d_in[1];
    const float* w_ih_f = (const float*)d_in[2];
    const float* w_hh_f = (const float*)d_in[3];
    const float* b_ih_f = (const float*)d_in[4];
    const float* b_hh_f = (const float*)d_in[5];
    const float* w_ih_b = (const float*)d_in[6];
    const float* w_hh_b = (const float*)d_in[7];
    const float* b_ih_b = (const float*)d_in[8];
    const float* b_hh_b = (const float*)d_in[9];
    const float* w_fc   = (const float*)d_in[10];
    const float* b_fc   = (const float*)d_in[11];
    float* out = (float*)d_out;

    k_proj<<<(VV + 7) / 8, 256>>>(emb, w_ih_f, b_ih_f, b_hh_f);
    k_nop<<<1, 32>>>();   // slot alignment: keep k_scan as our 4th launch
    k_nop<<<1, 32>>>();   // so ncu (-s 5 -c 1) captures it
    k_scan<<<BB / 4, 256>>>(x, w_hh_f);
    k_tail<<<BB, 256>>>(x, emb, w_ih_b, b_ih_b, b_hh_b, w_fc, b_fc, out);
}

// round 12
// speedup vs baseline: 2.6198x; 2.6198x over previous
#include <cuda_runtime.h>

// Problem constants
#define BB 256      // batch
#define TT 2000     // seq len
#define HH 64       // hidden
#define G4 256      // 4*H
#define VV 2000     // vocab

// Scratch (allocation-free rule: __device__ globals)
__device__ float g_proj[(size_t)VV * G4];   // [v][j] fp32 (gate-prescaled), 2 MB
__device__ float g_hf[BB * HH];

typedef unsigned long long u64;

__device__ __forceinline__ u64 fma2(u64 a, u64 b, u64 c) {
    u64 d;
    asm("fma.rn.f32x2 %0, %1, %2, %3;" : "=l"(d) : "l"(a), "l"(b), "l"(c));
    return d;
}
__device__ __forceinline__ u64 add2(u64 a, u64 b) {
    u64 d;
    asm("add.rn.f32x2 %0, %1, %2;" : "=l"(d) : "l"(a), "l"(b));
    return d;
}
__device__ __forceinline__ u64 pack2(float lo, float hi) {
    u64 d;
    asm("mov.b64 %0, {%1, %2};" : "=l"(d) : "f"(lo), "f"(hi));
    return d;
}
__device__ __forceinline__ float hsum2(u64 a) {
    float lo, hi;
    asm("mov.b64 {%0, %1}, %2;" : "=f"(lo), "=f"(hi) : "l"(a));
    return lo + hi;
}
__device__ __forceinline__ float ex2_(float x) {
    float r; asm("ex2.approx.f32 %0, %1;" : "=f"(r) : "f"(x)); return r;
}
__device__ __forceinline__ float rcp_(float x) {
    float r; asm("rcp.approx.f32 %0, %1;" : "=f"(r) : "f"(x)); return r;
}
__device__ __forceinline__ float tanha_(float x) {
    float r; asm("tanh.approx.f32 %0, %1;" : "=f"(r) : "f"(x)); return r;
}
__device__ __forceinline__ float sigmoid_(float x) {
    return rcp_(1.0f + ex2_(-1.4426950408889634f * x));
}
__device__ __forceinline__ float tanh_(float x) {
    return fmaf(2.0f, rcp_(1.0f + ex2_(-2.8853900817779268f * x)), -1.0f);
}

// no-op kernels: keep ncu's capture slot (-s 5 -c 1) on k_scan (our 4th launch)
__global__ void k_nop() {}

// ---------------------------------------------------------------------------
// K0: proj[v][j] = sg_j * (sum_k emb[v][k] * w_ih_f[j][k] + b_ih_f[j] + b_hh_f[j])
// sg_j = 0.5 for sigmoid gates (i,f,o), 1.0 for candidate gate (g):
// sigmoid(x) = 0.5*tanh(0.5x)+0.5 pre-scale baked in at the producer.
// ---------------------------------------------------------------------------
__global__ void __launch_bounds__(256) k_proj(
    const float* __restrict__ emb, const float* __restrict__ w,
    const float* __restrict__ b1, const float* __restrict__ b2)
{
    __shared__ __align__(16) float sh_e[8 * 64];
    const int j = threadIdx.x;

    u64 w2[32];
#pragma unroll
    for (int k2 = 0; k2 < 32; ++k2) {
        float2 wv = *(const float2*)&w[j * 64 + 2 * k2];
        w2[k2] = pack2(wv.x, wv.y);
    }
    const float bias = b1[j] + b2[j];
    const float sg = ((j >> 6) == 2) ? 1.0f : 0.5f;

    const int v0 = blockIdx.x * 8;
#pragma unroll
    for (int i = j; i < 512; i += 256) {
        int r = i >> 6, k = i & 63;
        int v = v0 + r;
        sh_e[i] = (v == 0 || v >= VV) ? 0.0f : emb[v * HH + k];
    }
    __syncthreads();
    const ulonglong2* ep = (const ulonglong2*)sh_e;
#pragma unroll
    for (int r = 0; r < 8; ++r) {
        int v = v0 + r;
        if (v >= VV) break;
        u64 acc = 0ull;
#pragma unroll
        for (int k4 = 0; k4 < 16; ++k4) {
            ulonglong2 ev = ep[r * 16 + k4];
            acc = fma2(w2[2 * k4], ev.x, acc);
            acc = fma2(w2[2 * k4 + 1], ev.y, acc);
        }
        g_proj[(size_t)v * G4 + j] = sg * (hsum2(acc) + bias);
    }
}

// ---------------------------------------------------------------------------
// K2: forward LSTM scan (R7 shape + issue trims).
// 256 CTAs x 128 threads, ONE batch row per CTA, 2 CTAs co-resident per SM
// (independent barriers/chains hide each other's latency). Quad-gate lanes:
// gate = l&3, unit pair (u0, u0+1). Gate exchange via shfl; cell update
// unconditional (garbage in non-gate0 lanes never stored); predicated STS.
// Trims: sg prescale moved into proj table; xc folded into accumulator
// init (no post-tree FADD); padded xs (no min clamp); unroll 2 (static
// ping-pong addresses).
// ---------------------------------------------------------------------------
__global__ void __launch_bounds__(128, 2) k_scan(
    const int* __restrict__ x, const float* __restrict__ whh)
{
    __shared__ __align__(16) float h_sh[2][64];  // [buf][unit]
    __shared__ int xs[TT + 2];                   // this row's indices, padded
    const int tid = threadIdx.x;
    const int w = tid >> 5, l = tid & 31;
    const int gate = l & 3;                // 0:i 1:f 2:g 3:o
    const int u0 = 2 * (w * 8 + (l >> 2)); // even unit 0..62
    const int b = blockIdx.x;
    const int j0 = gate * 64 + u0;         // adjacent pair j0, j0+1

    // stage x indices, pad 2 trailing entries (clamp-free prefetch)
    {
        const int* xr = x + (size_t)b * TT;
        for (int i = tid; i < TT; i += 128) xs[i] = xr[i];
        if (tid < 2) xs[TT + tid] = xr[TT - 1];
    }

    // gate==2 (candidate) uses tanh(p); others sigmoid(p)=0.5*tanh(0.5p)+0.5.
    const float sg = (gate == 2) ? 1.0f : 0.5f;
    const float mv = (gate == 2) ? 1.0f : 0.5f;
    const float av = (gate == 2) ? 0.0f : 0.5f;

    // weight rows j0, j0+1 in registers (k-packed f32x2), pre-scaled by sg
    u64 wa[32], wb[32];
#pragma unroll
    for (int k2 = 0; k2 < 32; ++k2) {
        float2 va = *(const float2*)&whh[j0 * 64 + 2 * k2];
        float2 vb = *(const float2*)&whh[(j0 + 1) * 64 + 2 * k2];
        wa[k2] = pack2(sg * va.x, sg * va.y);
        wb[k2] = pack2(sg * vb.x, sg * vb.y);
    }

    // zero step-0 read buffer
    if (tid < 64) h_sh[0][tid] = 0.0f;
    float c0 = 0.0f, c1 = 0.0f;

    const float* __restrict__ proj = g_proj;

    __syncthreads();  // x stage + h init visible

    // distance-2 prefetch of input projections (pre-scaled in table)
    float2 xc = *(const float2*)&proj[xs[0] * G4 + j0];
    float2 xn = *(const float2*)&proj[xs[1] * G4 + j0];

#pragma unroll 2
    for (int t = 0; t < TT - 1; ++t) {
        float2 xf = *(const float2*)&proj[xs[t + 2] * G4 + j0];  // padded

        // recurrent dots: p = h . (sg*whh[j]) + xc
        // xc folded into accumulator init -> no post-tree FADD
        const ulonglong2* hp = (const ulonglong2*)h_sh[t & 1];
        u64 a0 = pack2(xc.x, 0.0f), a1 = 0ull, a2 = 0ull, a3 = 0ull;
        u64 d0 = pack2(xc.y, 0.0f), d1 = 0ull, d2 = 0ull, d3 = 0ull;
#pragma unroll
        for (int k4 = 0; k4 < 8; ++k4) {
            ulonglong2 hv0 = hp[k4];
            ulonglong2 hv1 = hp[8 + k4];
            a0 = fma2(wa[2 * k4],      hv0.x, a0);
            a1 = fma2(wa[2 * k4 + 1],  hv0.y, a1);
            a2 = fma2(wa[16 + 2 * k4], hv1.x, a2);
            a3 = fma2(wa[17 + 2 * k4], hv1.y, a3);
            d0 = fma2(wb[2 * k4],      hv0.x, d0);
            d1 = fma2(wb[2 * k4 + 1],  hv0.y, d1);
            d2 = fma2(wb[16 + 2 * k4], hv1.x, d2);
            d3 = fma2(wb[17 + 2 * k4], hv1.y, d3);
        }
        float p0 = hsum2(add2(add2(a0, a1), add2(a2, a3)));
        float p1 = hsum2(add2(add2(d0, d1), add2(d2, d3)));

        // one-MUFU activation
        float v0 = fmaf(mv, tanha_(p0), av);
        float v1 = fmaf(mv, tanha_(p1), av);

        // quad exchange: gate0 lanes get (f,g,o); others wrapped garbage
        float f0 = __shfl_down_sync(0xffffffffu, v0, 1);
        float g0 = __shfl_down_sync(0xffffffffu, v0, 2);
        float o0 = __shfl_down_sync(0xffffffffu, v0, 3);
        float f1 = __shfl_down_sync(0xffffffffu, v1, 1);
        float g1 = __shfl_down_sync(0xffffffffu, v1, 2);
        float o1 = __shfl_down_sync(0xffffffffu, v1, 3);

        // unconditional cell update (garbage off-lanes never stored)
        c0 = f0 * c0 + v0 * g0;
        c1 = f1 * c1 + v1 * g1;
        float2 hv;
        hv.x = o0 * tanha_(c0);
        hv.y = o1 * tanha_(c1);
        if (gate == 0)                      // single predicated STS.64
            *(float2*)&h_sh[(t + 1) & 1][u0] = hv;
        __syncthreads();

        xc = xn; xn = xf;
    }

    // peeled final step t = TT-1: write h straight to global
    {
        const ulonglong2* hp = (const ulonglong2*)h_sh[(TT - 1) & 1];
        u64 a0 = pack2(xc.x, 0.0f), a1 = 0ull, a2 = 0ull, a3 = 0ull;
        u64 d0 = pack2(xc.y, 0.0f), d1 = 0ull, d2 = 0ull, d3 = 0ull;
#pragma unroll
        for (int k4 = 0; k4 < 8; ++k4) {
            ulonglong2 hv0 = hp[k4];
            ulonglong2 hv1 = hp[8 + k4];
            a0 = fma2(wa[2 * k4],      hv0.x, a0);
            a1 = fma2(wa[2 * k4 + 1],  hv0.y, a1);
            a2 = fma2(wa[16 + 2 * k4], hv1.x, a2);
            a3 = fma2(wa[17 + 2 * k4], hv1.y, a3);
            d0 = fma2(wb[2 * k4],      hv0.x, d0);
            d1 = fma2(wb[2 * k4 + 1],  hv0.y, d1);
            d2 = fma2(wb[16 + 2 * k4], hv1.x, d2);
            d3 = fma2(wb[17 + 2 * k4], hv1.y, d3);
        }
        float p0 = hsum2(add2(add2(a0, a1), add2(a2, a3)));
        float p1 = hsum2(add2(add2(d0, d1), add2(d2, d3)));
        float v0 = fmaf(mv, tanha_(p0), av);
        float v1 = fmaf(mv, tanha_(p1), av);
        float f0 = __shfl_down_sync(0xffffffffu, v0, 1);
        float g0 = __shfl_down_sync(0xffffffffu, v0, 2);
        float o0 = __shfl_down_sync(0xffffffffu, v0, 3);
        float f1 = __shfl_down_sync(0xffffffffu, v1, 1);
        float g1 = __shfl_down_sync(0xffffffffu, v1, 2);
        float o1 = __shfl_down_sync(0xffffffffu, v1, 3);
        c0 = f0 * c0 + v0 * g0;
        c1 = f1 * c1 + v1 * g1;
        float2 hv;
        hv.x = o0 * tanha_(c0);
        hv.y = o1 * tanha_(c1);
        if (gate == 0)
            *(float2*)&g_hf[b * HH + u0] = hv;
    }
}

// ---------------------------------------------------------------------------
// K3: fused tail. One block per batch row:
//   1) backward LSTM single step (hs_b[0]) from zero state at t=T-1
//   2) fc: out[b][c] = concat(hf[b], hb[b]) . w_fc[c] + b_fc[c]
// ---------------------------------------------------------------------------
__global__ void __launch_bounds__(256) k_tail(
    const int* __restrict__ x, const float* __restrict__ emb,
    const float* __restrict__ w, const float* __restrict__ b1,
    const float* __restrict__ b2, const float* __restrict__ wfc,
    const float* __restrict__ bfc, float* __restrict__ out)
{
    __shared__ __align__(16) float e_sh[64];
    __shared__ float g_sh[256];
    __shared__ float hb_sh[64];
    const int j = threadIdx.x;
    const int b = blockIdx.x;

    if (j < 64) {
        int idx = x[b * TT + (TT - 1)];
        e_sh[j] = (idx == 0) ? 0.0f : emb[idx * HH + j];
    }
    __syncthreads();

    float acc = b1[j] + b2[j];
    const ulonglong2* ep = (const ulonglong2*)e_sh;
    u64 a2 = 0ull;
#pragma unroll
    for (int k4 = 0; k4 < 16; ++k4) {
        float2 wv0 = *(const float2*)&w[j * 64 + 4 * k4];
        float2 wv1 = *(const float2*)&w[j * 64 + 4 * k4 + 2];
        ulonglong2 ev = ep[k4];
        a2 = fma2(pack2(wv0.x, wv0.y), ev.x, a2);
        a2 = fma2(pack2(wv1.x, wv1.y), ev.y, a2);
    }
    acc += hsum2(a2);

    const int gate = j >> 6;
    g_sh[j] = (gate == 2) ? tanh_(acc) : sigmoid_(acc);
    __syncthreads();

    if (j < 64) {
        float iv = g_sh[j];
        float gv = g_sh[128 + j];
        float ov = g_sh[192 + j];
        float cc = iv * gv;               // f*c0 = 0
        hb_sh[j] = ov * tanh_(cc);
    }
    __syncthreads();

    if (j < 12) {
        float s = bfc[j];
        const float* hf = g_hf + b * HH;
#pragma unroll
        for (int k = 0; k < 64; ++k)
            s += hf[k] * wfc[j * 128 + k];
#pragma unroll
        for (int k = 0; k < 64; ++k)
            s += hb_sh[k] * wfc[j * 128 + 64 + k];
        out[b * 12 + j] = s;
    }
}

// ---------------------------------------------------------------------------
extern "C" void kernel_launch(void* const* d_in, const int* in_sizes, int n_in,
                              void* d_out, int out_size)
{
    const int*   x      = (const int*)d_in[0];
    const float* emb    = (const float*)d_in[1];
    const float* w_ih_f = (const float*)d_in[2];
    const float* w_hh_f = (const float*)d_in[3];
    const float* b_ih_f = (const float*)d_in[4];
    const float* b_hh_f = (const float*)d_in[5];
    const float* w_ih_b = (const float*)d_in[6];
    const float* w_hh_b = (const float*)d_in[7];
    const float* b_ih_b = (const float*)d_in[8];
    const float* b_hh_b = (const float*)d_in[9];
    const float* w_fc   = (const float*)d_in[10];
    const float* b_fc   = (const float*)d_in[11];
    float* out = (float*)d_out;

    k_proj<<<(VV + 7) / 8, 256>>>(emb, w_ih_f, b_ih_f, b_hh_f);
    k_nop<<<1, 32>>>();   // slot alignment: keep k_scan as our 4th launch
    k_nop<<<1, 32>>>();   // so ncu (-s 5 -c 1) captures it
    k_scan<<<BB, 128>>>(x, w_hh_f);
    k_tail<<<BB, 256>>>(x, emb, w_ih_b, b_ih_b, b_hh_b, w_fc, b_fc, out);
}